// round 1
// baseline (speedup 1.0000x reference)
#include <cuda_runtime.h>
#include <cuda_bf16.h>

// Problem constants
#define BATCH   8192
#define P_DIM   32
#define Q_DIM   32
#define R_DIM   8
#define H1_DIM  128
#define H2_DIM  64
#define PH_DIM  16
#define PAIRS   1024
#define OUT_U   8192   // PAIRS * R

// Pair kernel tiling
#define PK_TILE      128   // samples per CTA
#define PK_CHUNK     64    // pairs per CTA
#define PK_NCHUNK    (PAIRS / PK_CHUNK)      // 16
#define PK_NTILE     (BATCH / PK_TILE)       // 64

// MLP kernel tiling
#define MK_TILE      64    // samples per CTA
#define MK_NTILE     (BATCH / MK_TILE)       // 128

// Deterministic partial buffer: 16 interaction chunks + X + Z
__device__ float g_partial[(PK_NCHUNK + 2) * BATCH];

// ---------------------------------------------------------------------------
// Kernel 1: main-effect MLPs (x: 32->128->64->1, z: same). blockIdx.y = part.
// 128 threads, 64-sample tile. Writes g_partial[16 + part].
// ---------------------------------------------------------------------------
__global__ __launch_bounds__(128)
void mlp_kernel(const float* __restrict__ x, const float* __restrict__ z,
                const float* __restrict__ xw1, const float* __restrict__ xb1,
                const float* __restrict__ xw2, const float* __restrict__ xb2,
                const float* __restrict__ xw3, const float* __restrict__ xb3,
                const float* __restrict__ zw1, const float* __restrict__ zb1,
                const float* __restrict__ zw2, const float* __restrict__ zb2,
                const float* __restrict__ zw3, const float* __restrict__ zb3)
{
    extern __shared__ float sm[];
    float* in_sm = sm;                 // 64*32   = 2048
    float* h1_sm = sm + 2048;          // 64*128  = 8192
    float* w2_sm = sm + 10240;         // 128*64  = 8192
    float* h2_sm = sm + 18432;         // 64*68   = 4352 (padded rows)
    float* w3_sm = sm + 22784;         // 64

    const int tid  = threadIdx.x;
    const int tile = blockIdx.x;
    const int part = blockIdx.y;
    const int g0   = tile * MK_TILE;

    const float* in = part ? z   : x;
    const float* w1 = part ? zw1 : xw1;
    const float* b1 = part ? zb1 : xb1;
    const float* w2 = part ? zw2 : xw2;
    const float* b2 = part ? zb2 : xb2;
    const float* w3 = part ? zw3 : xw3;
    const float* b3 = part ? zb3 : xb3;

    // stage input tile and layer-2 weights
    for (int idx = tid; idx < MK_TILE * 32; idx += 128)
        in_sm[idx] = in[(size_t)g0 * 32 + idx];
    for (int idx = tid; idx < 128 * 64; idx += 128)
        w2_sm[idx] = w2[idx];
    if (tid < 64) w3_sm[tid] = w3[tid];

    // layer-1 weight column in registers (column tid of [32,128])
    float wc[32];
    #pragma unroll
    for (int l = 0; l < 32; ++l) wc[l] = w1[l * 128 + tid];
    const float bc = b1[tid];

    __syncthreads();

    // ---- phase 1: h1[s][tid] = relu(x[s]·w1col + b1) ----
    for (int s = 0; s < MK_TILE; ++s) {
        float acc = bc;
        const float4* xr = (const float4*)(in_sm + s * 32);
        #pragma unroll
        for (int l4 = 0; l4 < 8; ++l4) {
            float4 v = xr[l4];
            acc = fmaf(v.x, wc[l4 * 4 + 0], acc);
            acc = fmaf(v.y, wc[l4 * 4 + 1], acc);
            acc = fmaf(v.z, wc[l4 * 4 + 2], acc);
            acc = fmaf(v.w, wc[l4 * 4 + 3], acc);
        }
        h1_sm[s * 128 + tid] = fmaxf(acc, 0.0f);
    }
    __syncthreads();

    // ---- phase 2: h2[s][o0..o0+3] for 8 samples per thread ----
    {
        const int oq = tid & 15;           // o0 = oq*4
        const int sg = tid >> 4;           // sample group (8 samples)
        float4 bb = ((const float4*)b2)[oq];
        const float4* w24 = (const float4*)w2_sm;
        for (int ss = 0; ss < 8; ++ss) {
            const int s = sg * 8 + ss;
            float4 acc = bb;
            const float4* hr4 = (const float4*)(h1_sm + s * 128);
            #pragma unroll 8
            for (int l4 = 0; l4 < 32; ++l4) {
                float4 hv = hr4[l4];
                float4 wA = w24[(l4 * 4 + 0) * 16 + oq];
                float4 wB = w24[(l4 * 4 + 1) * 16 + oq];
                float4 wC = w24[(l4 * 4 + 2) * 16 + oq];
                float4 wD = w24[(l4 * 4 + 3) * 16 + oq];
                acc.x = fmaf(hv.x, wA.x, acc.x); acc.y = fmaf(hv.x, wA.y, acc.y);
                acc.z = fmaf(hv.x, wA.z, acc.z); acc.w = fmaf(hv.x, wA.w, acc.w);
                acc.x = fmaf(hv.y, wB.x, acc.x); acc.y = fmaf(hv.y, wB.y, acc.y);
                acc.z = fmaf(hv.y, wB.z, acc.z); acc.w = fmaf(hv.y, wB.w, acc.w);
                acc.x = fmaf(hv.z, wC.x, acc.x); acc.y = fmaf(hv.z, wC.y, acc.y);
                acc.z = fmaf(hv.z, wC.z, acc.z); acc.w = fmaf(hv.z, wC.w, acc.w);
                acc.x = fmaf(hv.w, wD.x, acc.x); acc.y = fmaf(hv.w, wD.y, acc.y);
                acc.z = fmaf(hv.w, wD.z, acc.z); acc.w = fmaf(hv.w, wD.w, acc.w);
            }
            acc.x = fmaxf(acc.x, 0.0f); acc.y = fmaxf(acc.y, 0.0f);
            acc.z = fmaxf(acc.z, 0.0f); acc.w = fmaxf(acc.w, 0.0f);
            *(float4*)(h2_sm + s * 68 + oq * 4) = acc;   // s*68 words = 272B, 16B aligned
        }
    }
    __syncthreads();

    // ---- phase 3: out = h2 · w3 + b3 ----
    if (tid < MK_TILE) {
        const int s = tid;
        float acc = b3[0];
        const float* hr = h2_sm + s * 68;
        #pragma unroll
        for (int o = 0; o < 64; ++o) acc = fmaf(hr[o], w3_sm[o], acc);
        g_partial[(PK_NCHUNK + part) * BATCH + g0 + s] = acc;
    }
}

// ---------------------------------------------------------------------------
// Kernel 2: structured interaction + 1024 per-pair MLPs.
// grid = (64 sample tiles, 16 pair chunks), 128 threads (1 sample/thread).
// Per pair: h[8] = relu(wx*x_i + wz*z_k + b); t = relu(h@pw1 + pb1); out += t·pw2
// ---------------------------------------------------------------------------
__global__ __launch_bounds__(128, 2)
void pair_kernel(const float* __restrict__ x, const float* __restrict__ z,
                 const float* __restrict__ xzw, const float* __restrict__ xzb,
                 const float* __restrict__ pw1, const float* __restrict__ pb1,
                 const float* __restrict__ pw2)
{
    extern __shared__ float sm[];
    float* x_sm   = sm;                    // 128*33 = 4224
    float* z_sm   = sm + 4224;             // 4224
    float* wx_sm  = sm + 8448;             // 512
    float* wz_sm  = sm + 8960;             // 512
    float* bb_sm  = sm + 9472;             // 512
    float* pw1_sm = sm + 9984;             // 8192
    float* pb1_sm = sm + 18176;            // 1024
    float* pw2_sm = sm + 19200;            // 1024  (total 20224 floats)

    const int tid   = threadIdx.x;
    const int tile  = blockIdx.x;
    const int chunk = blockIdx.y;
    const int g0    = tile * PK_TILE;
    const int p0    = chunk * PK_CHUNK;

    // stage x/z tiles (padded stride 33 -> conflict-free per-lane reads)
    {
        const float* xg = x + (size_t)g0 * 32;
        const float* zg = z + (size_t)g0 * 32;
        for (int idx = tid; idx < PK_TILE * 32; idx += 128) {
            int s = idx >> 5, c = idx & 31;
            x_sm[s * 33 + c] = xg[idx];
            z_sm[s * 33 + c] = zg[idx];
        }
    }
    // stage sparse interaction weights for this chunk (gather from dense xzw)
    for (int idx = tid; idx < PK_CHUNK * R_DIM; idx += 128) {
        int col = p0 * R_DIM + idx;
        int p   = col >> 3;
        int i   = p >> 5;
        int k   = p & 31;
        wx_sm[idx] = xzw[(size_t)i * OUT_U + col];
        wz_sm[idx] = xzw[(size_t)(32 + k) * OUT_U + col];
        bb_sm[idx] = xzb[col];
    }
    // stage per-pair MLP weights (contiguous in global)
    for (int idx = tid; idx < PK_CHUNK * R_DIM * PH_DIM; idx += 128)
        pw1_sm[idx] = pw1[(size_t)p0 * R_DIM * PH_DIM + idx];
    for (int idx = tid; idx < PK_CHUNK * PH_DIM; idx += 128) {
        pb1_sm[idx] = pb1[(size_t)p0 * PH_DIM + idx];
        pw2_sm[idx] = pw2[(size_t)p0 * PH_DIM + idx];
    }
    __syncthreads();

    const float4* wx4  = (const float4*)wx_sm;
    const float4* wz4  = (const float4*)wz_sm;
    const float4* bb4  = (const float4*)bb_sm;
    const float4* pw14 = (const float4*)pw1_sm;
    const float4* pb14 = (const float4*)pb1_sm;
    const float4* pw24 = (const float4*)pw2_sm;

    const float* xrow = x_sm + tid * 33;
    const float* zrow = z_sm + tid * 33;

    float outa = 0.0f, outb = 0.0f;

    #pragma unroll 1
    for (int pl = 0; pl < PK_CHUNK; ++pl) {
        const int p  = p0 + pl;
        const float xi = xrow[p >> 5];
        const float zk = zrow[p & 31];

        // h[0..7] = relu(wx*xi + wz*zk + b)
        float4 wxa = wx4[2 * pl], wxb = wx4[2 * pl + 1];
        float4 wza = wz4[2 * pl], wzb = wz4[2 * pl + 1];
        float4 ba  = bb4[2 * pl], bbv = bb4[2 * pl + 1];
        float h[8];
        h[0] = fmaxf(fmaf(wxa.x, xi, fmaf(wza.x, zk, ba.x)),  0.0f);
        h[1] = fmaxf(fmaf(wxa.y, xi, fmaf(wza.y, zk, ba.y)),  0.0f);
        h[2] = fmaxf(fmaf(wxa.z, xi, fmaf(wza.z, zk, ba.z)),  0.0f);
        h[3] = fmaxf(fmaf(wxa.w, xi, fmaf(wza.w, zk, ba.w)),  0.0f);
        h[4] = fmaxf(fmaf(wxb.x, xi, fmaf(wzb.x, zk, bbv.x)), 0.0f);
        h[5] = fmaxf(fmaf(wxb.y, xi, fmaf(wzb.y, zk, bbv.y)), 0.0f);
        h[6] = fmaxf(fmaf(wxb.z, xi, fmaf(wzb.z, zk, bbv.z)), 0.0f);
        h[7] = fmaxf(fmaf(wxb.w, xi, fmaf(wzb.w, zk, bbv.w)), 0.0f);

        // t[16] = h @ pw1 + pb1
        float4 a0 = pb14[pl * 4 + 0];
        float4 a1 = pb14[pl * 4 + 1];
        float4 a2 = pb14[pl * 4 + 2];
        float4 a3 = pb14[pl * 4 + 3];
        #pragma unroll
        for (int j = 0; j < 8; ++j) {
            const float hv = h[j];
            float4 w0 = pw14[(pl * 8 + j) * 4 + 0];
            float4 w1 = pw14[(pl * 8 + j) * 4 + 1];
            float4 w2 = pw14[(pl * 8 + j) * 4 + 2];
            float4 w3 = pw14[(pl * 8 + j) * 4 + 3];
            a0.x = fmaf(hv, w0.x, a0.x); a0.y = fmaf(hv, w0.y, a0.y);
            a0.z = fmaf(hv, w0.z, a0.z); a0.w = fmaf(hv, w0.w, a0.w);
            a1.x = fmaf(hv, w1.x, a1.x); a1.y = fmaf(hv, w1.y, a1.y);
            a1.z = fmaf(hv, w1.z, a1.z); a1.w = fmaf(hv, w1.w, a1.w);
            a2.x = fmaf(hv, w2.x, a2.x); a2.y = fmaf(hv, w2.y, a2.y);
            a2.z = fmaf(hv, w2.z, a2.z); a2.w = fmaf(hv, w2.w, a2.w);
            a3.x = fmaf(hv, w3.x, a3.x); a3.y = fmaf(hv, w3.y, a3.y);
            a3.z = fmaf(hv, w3.z, a3.z); a3.w = fmaf(hv, w3.w, a3.w);
        }

        // out += relu(t) · pw2   (two accumulator chains for ILP)
        float4 q0 = pw24[pl * 4 + 0];
        float4 q1 = pw24[pl * 4 + 1];
        float4 q2 = pw24[pl * 4 + 2];
        float4 q3 = pw24[pl * 4 + 3];
        outa = fmaf(fmaxf(a0.x, 0.0f), q0.x, outa);
        outb = fmaf(fmaxf(a0.y, 0.0f), q0.y, outb);
        outa = fmaf(fmaxf(a0.z, 0.0f), q0.z, outa);
        outb = fmaf(fmaxf(a0.w, 0.0f), q0.w, outb);
        outa = fmaf(fmaxf(a1.x, 0.0f), q1.x, outa);
        outb = fmaf(fmaxf(a1.y, 0.0f), q1.y, outb);
        outa = fmaf(fmaxf(a1.z, 0.0f), q1.z, outa);
        outb = fmaf(fmaxf(a1.w, 0.0f), q1.w, outb);
        outa = fmaf(fmaxf(a2.x, 0.0f), q2.x, outa);
        outb = fmaf(fmaxf(a2.y, 0.0f), q2.y, outb);
        outa = fmaf(fmaxf(a2.z, 0.0f), q2.z, outa);
        outb = fmaf(fmaxf(a2.w, 0.0f), q2.w, outb);
        outa = fmaf(fmaxf(a3.x, 0.0f), q3.x, outa);
        outb = fmaf(fmaxf(a3.y, 0.0f), q3.y, outb);
        outa = fmaf(fmaxf(a3.z, 0.0f), q3.z, outa);
        outb = fmaf(fmaxf(a3.w, 0.0f), q3.w, outb);
    }

    g_partial[chunk * BATCH + g0 + tid] = outa + outb;
}

// ---------------------------------------------------------------------------
// Kernel 3: deterministic final reduction over 18 partial slices.
// ---------------------------------------------------------------------------
__global__ __launch_bounds__(256)
void reduce_kernel(float* __restrict__ out)
{
    const int b = blockIdx.x * 256 + threadIdx.x;
    float s = 0.0f;
    #pragma unroll
    for (int c = 0; c < PK_NCHUNK + 2; ++c)
        s += g_partial[c * BATCH + b];
    out[b] = s;
}

// ---------------------------------------------------------------------------
extern "C" void kernel_launch(void* const* d_in, const int* in_sizes, int n_in,
                              void* d_out, int out_size)
{
    const float* x   = (const float*)d_in[0];
    const float* z   = (const float*)d_in[1];
    const float* xw1 = (const float*)d_in[2];
    const float* xb1 = (const float*)d_in[3];
    const float* xw2 = (const float*)d_in[4];
    const float* xb2 = (const float*)d_in[5];
    const float* xw3 = (const float*)d_in[6];
    const float* xb3 = (const float*)d_in[7];
    const float* zw1 = (const float*)d_in[8];
    const float* zb1 = (const float*)d_in[9];
    const float* zw2 = (const float*)d_in[10];
    const float* zb2 = (const float*)d_in[11];
    const float* zw3 = (const float*)d_in[12];
    const float* zb3 = (const float*)d_in[13];
    const float* xzw = (const float*)d_in[14];
    const float* xzb = (const float*)d_in[15];
    const float* pw1 = (const float*)d_in[16];
    const float* pb1 = (const float*)d_in[17];
    const float* pw2 = (const float*)d_in[18];
    float* out = (float*)d_out;

    const size_t smem_mlp  = 22848u * sizeof(float);   // 91392 B
    const size_t smem_pair = 20224u * sizeof(float);   // 80896 B

    cudaFuncSetAttribute(mlp_kernel,  cudaFuncAttributeMaxDynamicSharedMemorySize, (int)smem_mlp);
    cudaFuncSetAttribute(pair_kernel, cudaFuncAttributeMaxDynamicSharedMemorySize, (int)smem_pair);

    pair_kernel<<<dim3(PK_NTILE, PK_NCHUNK), 128, smem_pair>>>(x, z, xzw, xzb, pw1, pb1, pw2);
    mlp_kernel<<<dim3(MK_NTILE, 2), 128, smem_mlp>>>(x, z,
        xw1, xb1, xw2, xb2, xw3, xb3,
        zw1, zb1, zw2, zb2, zw3, zb3);
    reduce_kernel<<<BATCH / 256, 256>>>(out);
}

// round 2
// speedup vs baseline: 1.6382x; 1.6382x over previous
#include <cuda_runtime.h>
#include <cuda_bf16.h>

// Problem constants
#define BATCH   8192
#define R_DIM   8
#define PH_DIM  16
#define PAIRS   1024
#define OUT_U   8192   // PAIRS * R

// Pair kernel tiling
#define PK_TILE      256   // samples per CTA (2 per thread)
#define PK_CHUNK     32    // pairs per CTA (one x-column per chunk)
#define PK_NCHUNK    (PAIRS / PK_CHUNK)      // 32
#define PK_NTILE     (BATCH / PK_TILE)       // 32

// MLP kernel tiling
#define MK_TILE      64
#define MK_NTILE     (BATCH / MK_TILE)       // 128

// Deterministic partial buffer: 32 interaction chunks + X + Z
__device__ float g_partial[(PK_NCHUNK + 2) * BATCH];

// ---- packed f32x2 helpers ---------------------------------------------------
__device__ __forceinline__ unsigned long long pack2(float lo, float hi) {
    unsigned long long r;
    asm("mov.b64 %0, {%1, %2};" : "=l"(r) : "f"(lo), "f"(hi));
    return r;
}
__device__ __forceinline__ void unpack2(unsigned long long v, float& lo, float& hi) {
    asm("mov.b64 {%0, %1}, %2;" : "=f"(lo), "=f"(hi) : "l"(v));
}
__device__ __forceinline__ unsigned long long fma2(unsigned long long a,
                                                   unsigned long long b,
                                                   unsigned long long c) {
    unsigned long long d;
    asm("fma.rn.f32x2 %0, %1, %2, %3;" : "=l"(d) : "l"(a), "l"(b), "l"(c));
    return d;
}

// ---------------------------------------------------------------------------
// Kernel 1: main-effect MLPs (x: 32->128->64->1, z: same). blockIdx.y = part.
// ---------------------------------------------------------------------------
__global__ __launch_bounds__(128)
void mlp_kernel(const float* __restrict__ x, const float* __restrict__ z,
                const float* __restrict__ xw1, const float* __restrict__ xb1,
                const float* __restrict__ xw2, const float* __restrict__ xb2,
                const float* __restrict__ xw3, const float* __restrict__ xb3,
                const float* __restrict__ zw1, const float* __restrict__ zb1,
                const float* __restrict__ zw2, const float* __restrict__ zb2,
                const float* __restrict__ zw3, const float* __restrict__ zb3)
{
    extern __shared__ float sm[];
    float* in_sm = sm;                 // 64*32   = 2048
    float* h1_sm = sm + 2048;          // 64*128  = 8192
    float* w2_sm = sm + 10240;         // 128*64  = 8192
    float* h2_sm = sm + 18432;         // 64*68   = 4352
    float* w3_sm = sm + 22784;         // 64

    const int tid  = threadIdx.x;
    const int tile = blockIdx.x;
    const int part = blockIdx.y;
    const int g0   = tile * MK_TILE;

    const float* in = part ? z   : x;
    const float* w1 = part ? zw1 : xw1;
    const float* b1 = part ? zb1 : xb1;
    const float* w2 = part ? zw2 : xw2;
    const float* b2 = part ? zb2 : xb2;
    const float* w3 = part ? zw3 : xw3;
    const float* b3 = part ? zb3 : xb3;

    for (int idx = tid; idx < MK_TILE * 32; idx += 128)
        in_sm[idx] = in[(size_t)g0 * 32 + idx];
    for (int idx = tid; idx < 128 * 64; idx += 128)
        w2_sm[idx] = w2[idx];
    if (tid < 64) w3_sm[tid] = w3[tid];

    float wc[32];
    #pragma unroll
    for (int l = 0; l < 32; ++l) wc[l] = w1[l * 128 + tid];
    const float bc = b1[tid];

    __syncthreads();

    for (int s = 0; s < MK_TILE; ++s) {
        float acc = bc;
        const float4* xr = (const float4*)(in_sm + s * 32);
        #pragma unroll
        for (int l4 = 0; l4 < 8; ++l4) {
            float4 v = xr[l4];
            acc = fmaf(v.x, wc[l4 * 4 + 0], acc);
            acc = fmaf(v.y, wc[l4 * 4 + 1], acc);
            acc = fmaf(v.z, wc[l4 * 4 + 2], acc);
            acc = fmaf(v.w, wc[l4 * 4 + 3], acc);
        }
        h1_sm[s * 128 + tid] = fmaxf(acc, 0.0f);
    }
    __syncthreads();

    {
        const int oq = tid & 15;
        const int sg = tid >> 4;
        float4 bb = ((const float4*)b2)[oq];
        const float4* w24 = (const float4*)w2_sm;
        for (int ss = 0; ss < 8; ++ss) {
            const int s = sg * 8 + ss;
            float4 acc = bb;
            const float4* hr4 = (const float4*)(h1_sm + s * 128);
            #pragma unroll 8
            for (int l4 = 0; l4 < 32; ++l4) {
                float4 hv = hr4[l4];
                float4 wA = w24[(l4 * 4 + 0) * 16 + oq];
                float4 wB = w24[(l4 * 4 + 1) * 16 + oq];
                float4 wC = w24[(l4 * 4 + 2) * 16 + oq];
                float4 wD = w24[(l4 * 4 + 3) * 16 + oq];
                acc.x = fmaf(hv.x, wA.x, acc.x); acc.y = fmaf(hv.x, wA.y, acc.y);
                acc.z = fmaf(hv.x, wA.z, acc.z); acc.w = fmaf(hv.x, wA.w, acc.w);
                acc.x = fmaf(hv.y, wB.x, acc.x); acc.y = fmaf(hv.y, wB.y, acc.y);
                acc.z = fmaf(hv.y, wB.z, acc.z); acc.w = fmaf(hv.y, wB.w, acc.w);
                acc.x = fmaf(hv.z, wC.x, acc.x); acc.y = fmaf(hv.z, wC.y, acc.y);
                acc.z = fmaf(hv.z, wC.z, acc.z); acc.w = fmaf(hv.z, wC.w, acc.w);
                acc.x = fmaf(hv.w, wD.x, acc.x); acc.y = fmaf(hv.w, wD.y, acc.y);
                acc.z = fmaf(hv.w, wD.z, acc.z); acc.w = fmaf(hv.w, wD.w, acc.w);
            }
            acc.x = fmaxf(acc.x, 0.0f); acc.y = fmaxf(acc.y, 0.0f);
            acc.z = fmaxf(acc.z, 0.0f); acc.w = fmaxf(acc.w, 0.0f);
            *(float4*)(h2_sm + s * 68 + oq * 4) = acc;
        }
    }
    __syncthreads();

    if (tid < MK_TILE) {
        const int s = tid;
        float acc = b3[0];
        const float* hr = h2_sm + s * 68;
        #pragma unroll
        for (int o = 0; o < 64; ++o) acc = fmaf(hr[o], w3_sm[o], acc);
        g_partial[(PK_NCHUNK + part) * BATCH + g0 + s] = acc;
    }
}

// ---------------------------------------------------------------------------
// Kernel 2: structured interaction + per-pair MLPs.
// grid = (32 sample tiles, 32 pair chunks). 128 threads, 2 samples/thread.
// Chunk covers pairs [chunk*32, chunk*32+32): all share x-column i == chunk.
// Per pair: h[8] = relu(wx*xi + wz*zk + b); t = h@pw1 + pb1 (f32x2 packed);
//           out += relu(t) · pw2
// ---------------------------------------------------------------------------
__global__ __launch_bounds__(128, 3)
void pair_kernel(const float* __restrict__ x, const float* __restrict__ z,
                 const float* __restrict__ xzw, const float* __restrict__ xzb,
                 const float* __restrict__ pw1, const float* __restrict__ pb1,
                 const float* __restrict__ pw2)
{
    extern __shared__ float sm[];
    float* z_sm   = sm;                    // 256*33 = 8448
    float* wx_sm  = sm + 8448;             // 256
    float* wz_sm  = sm + 8704;             // 256
    float* bb_sm  = sm + 8960;             // 256
    float* pw1_sm = sm + 9216;             // 4096
    float* pb1_sm = sm + 13312;            // 512
    float* pw2_sm = sm + 13824;            // 512  (total 14336 floats = 57344 B)

    const int tid   = threadIdx.x;
    const int tile  = blockIdx.x;
    const int chunk = blockIdx.y;
    const int g0    = tile * PK_TILE;
    const int p0    = chunk * PK_CHUNK;

    // stage z tile (padded stride 33)
    {
        const float* zg = z + (size_t)g0 * 32;
        for (int idx = tid; idx < PK_TILE * 32; idx += 128) {
            int s = idx >> 5, c = idx & 31;
            z_sm[s * 33 + c] = zg[idx];
        }
    }
    // gather sparse interaction weights (x-row is `chunk` for the whole chunk)
    for (int idx = tid; idx < PK_CHUNK * R_DIM; idx += 128) {
        int col = p0 * R_DIM + idx;
        int k   = idx >> 3;                 // pair index within chunk == z index
        wx_sm[idx] = xzw[(size_t)chunk * OUT_U + col];
        wz_sm[idx] = xzw[(size_t)(32 + k) * OUT_U + col];
        bb_sm[idx] = xzb[col];
    }
    for (int idx = tid; idx < PK_CHUNK * R_DIM * PH_DIM; idx += 128)
        pw1_sm[idx] = pw1[(size_t)p0 * R_DIM * PH_DIM + idx];
    for (int idx = tid; idx < PK_CHUNK * PH_DIM; idx += 128) {
        pb1_sm[idx] = pb1[(size_t)p0 * PH_DIM + idx];
        pw2_sm[idx] = pw2[(size_t)p0 * PH_DIM + idx];
    }

    // this chunk touches exactly one x column: x[:, chunk]
    const float xi0 = x[(size_t)(g0 + tid) * 32 + chunk];
    const float xi1 = x[(size_t)(g0 + tid + 128) * 32 + chunk];

    __syncthreads();

    const float4*      wx4  = (const float4*)wx_sm;
    const float4*      wz4  = (const float4*)wz_sm;
    const float4*      bb4  = (const float4*)bb_sm;
    const ulonglong2*  pw1v = (const ulonglong2*)pw1_sm;   // 4 per (pair,j)
    const ulonglong2*  pb1v = (const ulonglong2*)pb1_sm;   // 4 per pair
    const float4*      pw24 = (const float4*)pw2_sm;

    const float* zrow0 = z_sm + tid * 33;
    const float* zrow1 = z_sm + (tid + 128) * 33;

    float outA0 = 0.0f, outB0 = 0.0f;
    float outA1 = 0.0f, outB1 = 0.0f;

    #pragma unroll 1
    for (int pl = 0; pl < PK_CHUNK; ++pl) {
        const float zk0 = zrow0[pl];
        const float zk1 = zrow1[pl];

        float4 wxa = wx4[2 * pl], wxb = wx4[2 * pl + 1];
        float4 wza = wz4[2 * pl], wzb = wz4[2 * pl + 1];
        float4 ba  = bb4[2 * pl], bc  = bb4[2 * pl + 1];

        // h for both samples (scalar, reuses weight regs)
        float h0[8], h1[8];
        h0[0] = fmaxf(fmaf(wxa.x, xi0, fmaf(wza.x, zk0, ba.x)), 0.0f);
        h0[1] = fmaxf(fmaf(wxa.y, xi0, fmaf(wza.y, zk0, ba.y)), 0.0f);
        h0[2] = fmaxf(fmaf(wxa.z, xi0, fmaf(wza.z, zk0, ba.z)), 0.0f);
        h0[3] = fmaxf(fmaf(wxa.w, xi0, fmaf(wza.w, zk0, ba.w)), 0.0f);
        h0[4] = fmaxf(fmaf(wxb.x, xi0, fmaf(wzb.x, zk0, bc.x)), 0.0f);
        h0[5] = fmaxf(fmaf(wxb.y, xi0, fmaf(wzb.y, zk0, bc.y)), 0.0f);
        h0[6] = fmaxf(fmaf(wxb.z, xi0, fmaf(wzb.z, zk0, bc.z)), 0.0f);
        h0[7] = fmaxf(fmaf(wxb.w, xi0, fmaf(wzb.w, zk0, bc.w)), 0.0f);
        h1[0] = fmaxf(fmaf(wxa.x, xi1, fmaf(wza.x, zk1, ba.x)), 0.0f);
        h1[1] = fmaxf(fmaf(wxa.y, xi1, fmaf(wza.y, zk1, ba.y)), 0.0f);
        h1[2] = fmaxf(fmaf(wxa.z, xi1, fmaf(wza.z, zk1, ba.z)), 0.0f);
        h1[3] = fmaxf(fmaf(wxa.w, xi1, fmaf(wza.w, zk1, ba.w)), 0.0f);
        h1[4] = fmaxf(fmaf(wxb.x, xi1, fmaf(wzb.x, zk1, bc.x)), 0.0f);
        h1[5] = fmaxf(fmaf(wxb.y, xi1, fmaf(wzb.y, zk1, bc.y)), 0.0f);
        h1[6] = fmaxf(fmaf(wxb.z, xi1, fmaf(wzb.z, zk1, bc.z)), 0.0f);
        h1[7] = fmaxf(fmaf(wxb.w, xi1, fmaf(wzb.w, zk1, bc.w)), 0.0f);

        // accumulators: 8 f32x2 per sample (16 PH units)
        unsigned long long t0[8], t1[8];
        {
            const ulonglong2* pb = pb1v + pl * 4;
            ulonglong2 q;
            q = pb[0]; t0[0] = q.x; t0[1] = q.y; t1[0] = q.x; t1[1] = q.y;
            q = pb[1]; t0[2] = q.x; t0[3] = q.y; t1[2] = q.x; t1[3] = q.y;
            q = pb[2]; t0[4] = q.x; t0[5] = q.y; t1[4] = q.x; t1[5] = q.y;
            q = pb[3]; t0[6] = q.x; t0[7] = q.y; t1[6] = q.x; t1[7] = q.y;
        }

        #pragma unroll
        for (int j = 0; j < 8; ++j) {
            const ulonglong2* wv = pw1v + (pl * 8 + j) * 4;
            ulonglong2 wA = wv[0], wB = wv[1], wC = wv[2], wD = wv[3];
            unsigned long long hv0 = pack2(h0[j], h0[j]);
            unsigned long long hv1 = pack2(h1[j], h1[j]);
            t0[0] = fma2(hv0, wA.x, t0[0]); t0[1] = fma2(hv0, wA.y, t0[1]);
            t0[2] = fma2(hv0, wB.x, t0[2]); t0[3] = fma2(hv0, wB.y, t0[3]);
            t0[4] = fma2(hv0, wC.x, t0[4]); t0[5] = fma2(hv0, wC.y, t0[5]);
            t0[6] = fma2(hv0, wD.x, t0[6]); t0[7] = fma2(hv0, wD.y, t0[7]);
            t1[0] = fma2(hv1, wA.x, t1[0]); t1[1] = fma2(hv1, wA.y, t1[1]);
            t1[2] = fma2(hv1, wB.x, t1[2]); t1[3] = fma2(hv1, wB.y, t1[3]);
            t1[4] = fma2(hv1, wC.x, t1[4]); t1[5] = fma2(hv1, wC.y, t1[5]);
            t1[6] = fma2(hv1, wD.x, t1[6]); t1[7] = fma2(hv1, wD.y, t1[7]);
        }

        // out += relu(t) · pw2
        float4 q0 = pw24[pl * 4 + 0];
        float4 q1 = pw24[pl * 4 + 1];
        float4 q2 = pw24[pl * 4 + 2];
        float4 q3 = pw24[pl * 4 + 3];
        float lo, hi;
        unpack2(t0[0], lo, hi);
        outA0 = fmaf(fmaxf(lo, 0.f), q0.x, outA0); outB0 = fmaf(fmaxf(hi, 0.f), q0.y, outB0);
        unpack2(t0[1], lo, hi);
        outA0 = fmaf(fmaxf(lo, 0.f), q0.z, outA0); outB0 = fmaf(fmaxf(hi, 0.f), q0.w, outB0);
        unpack2(t0[2], lo, hi);
        outA0 = fmaf(fmaxf(lo, 0.f), q1.x, outA0); outB0 = fmaf(fmaxf(hi, 0.f), q1.y, outB0);
        unpack2(t0[3], lo, hi);
        outA0 = fmaf(fmaxf(lo, 0.f), q1.z, outA0); outB0 = fmaf(fmaxf(hi, 0.f), q1.w, outB0);
        unpack2(t0[4], lo, hi);
        outA0 = fmaf(fmaxf(lo, 0.f), q2.x, outA0); outB0 = fmaf(fmaxf(hi, 0.f), q2.y, outB0);
        unpack2(t0[5], lo, hi);
        outA0 = fmaf(fmaxf(lo, 0.f), q2.z, outA0); outB0 = fmaf(fmaxf(hi, 0.f), q2.w, outB0);
        unpack2(t0[6], lo, hi);
        outA0 = fmaf(fmaxf(lo, 0.f), q3.x, outA0); outB0 = fmaf(fmaxf(hi, 0.f), q3.y, outB0);
        unpack2(t0[7], lo, hi);
        outA0 = fmaf(fmaxf(lo, 0.f), q3.z, outA0); outB0 = fmaf(fmaxf(hi, 0.f), q3.w, outB0);

        unpack2(t1[0], lo, hi);
        outA1 = fmaf(fmaxf(lo, 0.f), q0.x, outA1); outB1 = fmaf(fmaxf(hi, 0.f), q0.y, outB1);
        unpack2(t1[1], lo, hi);
        outA1 = fmaf(fmaxf(lo, 0.f), q0.z, outA1); outB1 = fmaf(fmaxf(hi, 0.f), q0.w, outB1);
        unpack2(t1[2], lo, hi);
        outA1 = fmaf(fmaxf(lo, 0.f), q1.x, outA1); outB1 = fmaf(fmaxf(hi, 0.f), q1.y, outB1);
        unpack2(t1[3], lo, hi);
        outA1 = fmaf(fmaxf(lo, 0.f), q1.z, outA1); outB1 = fmaf(fmaxf(hi, 0.f), q1.w, outB1);
        unpack2(t1[4], lo, hi);
        outA1 = fmaf(fmaxf(lo, 0.f), q2.x, outA1); outB1 = fmaf(fmaxf(hi, 0.f), q2.y, outB1);
        unpack2(t1[5], lo, hi);
        outA1 = fmaf(fmaxf(lo, 0.f), q2.z, outA1); outB1 = fmaf(fmaxf(hi, 0.f), q2.w, outB1);
        unpack2(t1[6], lo, hi);
        outA1 = fmaf(fmaxf(lo, 0.f), q3.x, outA1); outB1 = fmaf(fmaxf(hi, 0.f), q3.y, outB1);
        unpack2(t1[7], lo, hi);
        outA1 = fmaf(fmaxf(lo, 0.f), q3.z, outA1); outB1 = fmaf(fmaxf(hi, 0.f), q3.w, outB1);
    }

    g_partial[chunk * BATCH + g0 + tid]       = outA0 + outB0;
    g_partial[chunk * BATCH + g0 + tid + 128] = outA1 + outB1;
}

// ---------------------------------------------------------------------------
// Kernel 3: deterministic final reduction over 34 partial slices.
// ---------------------------------------------------------------------------
__global__ __launch_bounds__(256)
void reduce_kernel(float* __restrict__ out)
{
    const int b = blockIdx.x * 256 + threadIdx.x;
    float s = 0.0f;
    #pragma unroll
    for (int c = 0; c < PK_NCHUNK + 2; ++c)
        s += g_partial[c * BATCH + b];
    out[b] = s;
}

// ---------------------------------------------------------------------------
extern "C" void kernel_launch(void* const* d_in, const int* in_sizes, int n_in,
                              void* d_out, int out_size)
{
    const float* x   = (const float*)d_in[0];
    const float* z   = (const float*)d_in[1];
    const float* xw1 = (const float*)d_in[2];
    const float* xb1 = (const float*)d_in[3];
    const float* xw2 = (const float*)d_in[4];
    const float* xb2 = (const float*)d_in[5];
    const float* xw3 = (const float*)d_in[6];
    const float* xb3 = (const float*)d_in[7];
    const float* zw1 = (const float*)d_in[8];
    const float* zb1 = (const float*)d_in[9];
    const float* zw2 = (const float*)d_in[10];
    const float* zb2 = (const float*)d_in[11];
    const float* zw3 = (const float*)d_in[12];
    const float* zb3 = (const float*)d_in[13];
    const float* xzw = (const float*)d_in[14];
    const float* xzb = (const float*)d_in[15];
    const float* pw1 = (const float*)d_in[16];
    const float* pb1 = (const float*)d_in[17];
    const float* pw2 = (const float*)d_in[18];
    float* out = (float*)d_out;

    const size_t smem_mlp  = 22848u * sizeof(float);   // 91392 B
    const size_t smem_pair = 14336u * sizeof(float);   // 57344 B

    cudaFuncSetAttribute(mlp_kernel,  cudaFuncAttributeMaxDynamicSharedMemorySize, (int)smem_mlp);
    cudaFuncSetAttribute(pair_kernel, cudaFuncAttributeMaxDynamicSharedMemorySize, (int)smem_pair);

    pair_kernel<<<dim3(PK_NTILE, PK_NCHUNK), 128, smem_pair>>>(x, z, xzw, xzb, pw1, pb1, pw2);
    mlp_kernel<<<dim3(MK_NTILE, 2), 128, smem_mlp>>>(x, z,
        xw1, xb1, xw2, xb2, xw3, xb3,
        zw1, zb1, zw2, zb2, zw3, zb3);
    reduce_kernel<<<BATCH / 256, 256>>>(out);
}

// round 3
// speedup vs baseline: 1.9454x; 1.1876x over previous
#include <cuda_runtime.h>
#include <cuda_bf16.h>

// Problem constants
#define BATCH   8192
#define R_DIM   8
#define PH_DIM  16
#define PAIRS   1024
#define OUT_U   8192   // PAIRS * R

// Pair kernel tiling
#define PK_TILE      256   // samples per CTA (2 adjacent per thread)
#define PK_CHUNK     32    // pairs per CTA (one x-column per chunk)
#define PK_NCHUNK    (PAIRS / PK_CHUNK)      // 32
#define PK_NTILE     (BATCH / PK_TILE)       // 32

// MLP kernel tiling
#define MK_TILE      64
#define MK_NTILE     (BATCH / MK_TILE)       // 128

// Deterministic partial buffer: 32 interaction chunks + X + Z
__device__ float g_partial[(PK_NCHUNK + 2) * BATCH];
// Transposed inputs: [32][8192]
__device__ float g_xT[32 * BATCH];
__device__ float g_zT[32 * BATCH];

typedef unsigned long long ull;

// ---- packed f32x2 helpers ---------------------------------------------------
__device__ __forceinline__ ull pack2(float lo, float hi) {
    ull r;
    asm("mov.b64 %0, {%1, %2};" : "=l"(r) : "f"(lo), "f"(hi));
    return r;
}
__device__ __forceinline__ void unpack2(ull v, float& lo, float& hi) {
    asm("mov.b64 {%0, %1}, %2;" : "=f"(lo), "=f"(hi) : "l"(v));
}
__device__ __forceinline__ ull fma2(ull a, ull b, ull c) {
    ull d;
    asm("fma.rn.f32x2 %0, %1, %2, %3;" : "=l"(d) : "l"(a), "l"(b), "l"(c));
    return d;
}

// ---------------------------------------------------------------------------
// Kernel 0: transpose x,z [8192][32] -> [32][8192]
// ---------------------------------------------------------------------------
__global__ __launch_bounds__(256)
void transpose_kernel(const float* __restrict__ x, const float* __restrict__ z)
{
    __shared__ float tx[64 * 33];
    __shared__ float tz[64 * 33];
    const int tid = threadIdx.x;
    const int g0  = blockIdx.x * 64;

    for (int idx = tid; idx < 64 * 32; idx += 256) {
        int s = idx >> 5, c = idx & 31;
        tx[s * 33 + c] = x[(size_t)g0 * 32 + idx];
        tz[s * 33 + c] = z[(size_t)g0 * 32 + idx];
    }
    __syncthreads();
    for (int idx = tid; idx < 64 * 32; idx += 256) {
        int c = idx >> 6, s = idx & 63;
        g_xT[(size_t)c * BATCH + g0 + s] = tx[s * 33 + c];
        g_zT[(size_t)c * BATCH + g0 + s] = tz[s * 33 + c];
    }
}

// ---------------------------------------------------------------------------
// Kernel 1: main-effect MLPs (32->128->64->1). blockIdx.y = part (x or z).
// ---------------------------------------------------------------------------
__global__ __launch_bounds__(128)
void mlp_kernel(const float* __restrict__ x, const float* __restrict__ z,
                const float* __restrict__ xw1, const float* __restrict__ xb1,
                const float* __restrict__ xw2, const float* __restrict__ xb2,
                const float* __restrict__ xw3, const float* __restrict__ xb3,
                const float* __restrict__ zw1, const float* __restrict__ zb1,
                const float* __restrict__ zw2, const float* __restrict__ zb2,
                const float* __restrict__ zw3, const float* __restrict__ zb3)
{
    extern __shared__ float sm[];
    float* in_sm = sm;                 // 64*32   = 2048
    float* h1_sm = sm + 2048;          // 64*128  = 8192
    float* w2_sm = sm + 10240;         // 128*64  = 8192
    float* h2_sm = sm + 18432;         // 64*68   = 4352
    float* w3_sm = sm + 22784;         // 64

    const int tid  = threadIdx.x;
    const int tile = blockIdx.x;
    const int part = blockIdx.y;
    const int g0   = tile * MK_TILE;

    const float* in = part ? z   : x;
    const float* w1 = part ? zw1 : xw1;
    const float* b1 = part ? zb1 : xb1;
    const float* w2 = part ? zw2 : xw2;
    const float* b2 = part ? zb2 : xb2;
    const float* w3 = part ? zw3 : xw3;
    const float* b3 = part ? zb3 : xb3;

    for (int idx = tid; idx < MK_TILE * 32; idx += 128)
        in_sm[idx] = in[(size_t)g0 * 32 + idx];
    for (int idx = tid; idx < 128 * 64; idx += 128)
        w2_sm[idx] = w2[idx];
    if (tid < 64) w3_sm[tid] = w3[tid];

    float wc[32];
    #pragma unroll
    for (int l = 0; l < 32; ++l) wc[l] = w1[l * 128 + tid];
    const float bc = b1[tid];

    __syncthreads();

    // ---- phase 1: h1[s][tid] = relu(x[s]·w1col + b1) ----
    for (int s = 0; s < MK_TILE; ++s) {
        float acc = bc;
        const float4* xr = (const float4*)(in_sm + s * 32);
        #pragma unroll
        for (int l4 = 0; l4 < 8; ++l4) {
            float4 v = xr[l4];
            acc = fmaf(v.x, wc[l4 * 4 + 0], acc);
            acc = fmaf(v.y, wc[l4 * 4 + 1], acc);
            acc = fmaf(v.z, wc[l4 * 4 + 2], acc);
            acc = fmaf(v.w, wc[l4 * 4 + 3], acc);
        }
        h1_sm[s * 128 + tid] = fmaxf(acc, 0.0f);
    }
    __syncthreads();

    // ---- phase 2: h2 = relu(h1 @ w2 + b2); loop-swapped, f32x2 ----
    {
        const int oq = tid & 15;           // outputs 4*oq .. 4*oq+3
        const int sg = tid >> 4;           // samples sg*8 .. sg*8+7
        float4 bb = ((const float4*)b2)[oq];
        ull accA[8], accB[8];
        const ull bA = pack2(bb.x, bb.y);
        const ull bB = pack2(bb.z, bb.w);
        #pragma unroll
        for (int ss = 0; ss < 8; ++ss) { accA[ss] = bA; accB[ss] = bB; }

        const float4* w24   = (const float4*)w2_sm;
        const float4* hbase = (const float4*)(h1_sm + sg * 8 * 128);

        #pragma unroll 2
        for (int l4 = 0; l4 < 32; ++l4) {
            float4 wA = w24[(l4 * 4 + 0) * 16 + oq];
            float4 wB = w24[(l4 * 4 + 1) * 16 + oq];
            float4 wC = w24[(l4 * 4 + 2) * 16 + oq];
            float4 wD = w24[(l4 * 4 + 3) * 16 + oq];
            const ulonglong2 wAp = *(const ulonglong2*)&wA;
            const ulonglong2 wBp = *(const ulonglong2*)&wB;
            const ulonglong2 wCp = *(const ulonglong2*)&wC;
            const ulonglong2 wDp = *(const ulonglong2*)&wD;
            #pragma unroll
            for (int ss = 0; ss < 8; ++ss) {
                float4 hv = hbase[ss * 32 + l4];
                ull hx = pack2(hv.x, hv.x);
                ull hy = pack2(hv.y, hv.y);
                ull hz = pack2(hv.z, hv.z);
                ull hw = pack2(hv.w, hv.w);
                accA[ss] = fma2(hx, wAp.x, accA[ss]); accB[ss] = fma2(hx, wAp.y, accB[ss]);
                accA[ss] = fma2(hy, wBp.x, accA[ss]); accB[ss] = fma2(hy, wBp.y, accB[ss]);
                accA[ss] = fma2(hz, wCp.x, accA[ss]); accB[ss] = fma2(hz, wCp.y, accB[ss]);
                accA[ss] = fma2(hw, wDp.x, accA[ss]); accB[ss] = fma2(hw, wDp.y, accB[ss]);
            }
        }
        #pragma unroll
        for (int ss = 0; ss < 8; ++ss) {
            const int s = sg * 8 + ss;
            float a0, a1, a2, a3;
            unpack2(accA[ss], a0, a1);
            unpack2(accB[ss], a2, a3);
            float4 r;
            r.x = fmaxf(a0, 0.0f); r.y = fmaxf(a1, 0.0f);
            r.z = fmaxf(a2, 0.0f); r.w = fmaxf(a3, 0.0f);
            *(float4*)(h2_sm + s * 68 + oq * 4) = r;
        }
    }
    __syncthreads();

    // ---- phase 3: out = h2 · w3 + b3 ----
    if (tid < MK_TILE) {
        const int s = tid;
        float acc = b3[0];
        const float* hr = h2_sm + s * 68;
        #pragma unroll
        for (int o = 0; o < 64; ++o) acc = fmaf(hr[o], w3_sm[o], acc);
        g_partial[(PK_NCHUNK + part) * BATCH + g0 + s] = acc;
    }
}

// ---------------------------------------------------------------------------
// Kernel 2: structured interaction + per-pair MLPs.
// grid = (32 sample tiles, 32 pair chunks). 128 threads, 2 adjacent samples.
// z/x read from transposed buffers (coalesced LDG.64), weights in smem.
// ---------------------------------------------------------------------------
__global__ __launch_bounds__(128, 5)
void pair_kernel(const float* __restrict__ xzw, const float* __restrict__ xzb,
                 const float* __restrict__ pw1, const float* __restrict__ pb1,
                 const float* __restrict__ pw2)
{
    __shared__ __align__(16) float sm[5888];   // 23552 B
    float* wx_sm  = sm;            // 256
    float* wz_sm  = sm + 256;      // 256
    float* bb_sm  = sm + 512;      // 256
    float* pw1_sm = sm + 768;      // 4096
    float* pb1_sm = sm + 4864;     // 512
    float* pw2_sm = sm + 5376;     // 512

    const int tid   = threadIdx.x;
    const int tile  = blockIdx.x;
    const int chunk = blockIdx.y;
    const int g0    = tile * PK_TILE;
    const int p0    = chunk * PK_CHUNK;

    // stage weights
    for (int idx = tid; idx < PK_CHUNK * R_DIM; idx += 128) {
        int col = p0 * R_DIM + idx;
        int k   = idx >> 3;                 // pair index within chunk == z index
        wx_sm[idx] = xzw[(size_t)chunk * OUT_U + col];
        wz_sm[idx] = xzw[(size_t)(32 + k) * OUT_U + col];
        bb_sm[idx] = xzb[col];
    }
    for (int idx = tid; idx < PK_CHUNK * R_DIM * PH_DIM; idx += 128)
        pw1_sm[idx] = pw1[(size_t)p0 * R_DIM * PH_DIM + idx];
    for (int idx = tid; idx < PK_CHUNK * PH_DIM; idx += 128) {
        pb1_sm[idx] = pb1[(size_t)p0 * PH_DIM + idx];
        pw2_sm[idx] = pw2[(size_t)p0 * PH_DIM + idx];
    }

    // samples s0 = g0 + 2*tid, s1 = s0 + 1
    const float2 xi2 = ((const float2*)(g_xT + (size_t)chunk * BATCH + g0))[tid];
    const float  xi0 = xi2.x, xi1 = xi2.y;
    const float2* zT2 = (const float2*)(g_zT + g0) + tid;  // row stride = 4096 float2

    __syncthreads();

    const float4*     wx4  = (const float4*)wx_sm;
    const float4*     wz4  = (const float4*)wz_sm;
    const float4*     bb4  = (const float4*)bb_sm;
    const ulonglong2* pw1v = (const ulonglong2*)pw1_sm;
    const ulonglong2* pb1v = (const ulonglong2*)pb1_sm;
    const float4*     pw24 = (const float4*)pw2_sm;

    float outA0 = 0.0f, outB0 = 0.0f;
    float outA1 = 0.0f, outB1 = 0.0f;

    float2 zk = zT2[0];

    #pragma unroll 1
    for (int pl = 0; pl < PK_CHUNK; ++pl) {
        // prefetch next pair's z (wraps on last iter; value unused)
        float2 zkn = zT2[((pl + 1) & 31) * (BATCH / 2)];
        const float zk0 = zk.x, zk1 = zk.y;

        float4 wxa = wx4[2 * pl], wxb = wx4[2 * pl + 1];
        float4 wza = wz4[2 * pl], wzb = wz4[2 * pl + 1];
        float4 ba  = bb4[2 * pl], bc  = bb4[2 * pl + 1];

        float h0[8], h1[8];
        h0[0] = fmaxf(fmaf(wxa.x, xi0, fmaf(wza.x, zk0, ba.x)), 0.0f);
        h0[1] = fmaxf(fmaf(wxa.y, xi0, fmaf(wza.y, zk0, ba.y)), 0.0f);
        h0[2] = fmaxf(fmaf(wxa.z, xi0, fmaf(wza.z, zk0, ba.z)), 0.0f);
        h0[3] = fmaxf(fmaf(wxa.w, xi0, fmaf(wza.w, zk0, ba.w)), 0.0f);
        h0[4] = fmaxf(fmaf(wxb.x, xi0, fmaf(wzb.x, zk0, bc.x)), 0.0f);
        h0[5] = fmaxf(fmaf(wxb.y, xi0, fmaf(wzb.y, zk0, bc.y)), 0.0f);
        h0[6] = fmaxf(fmaf(wxb.z, xi0, fmaf(wzb.z, zk0, bc.z)), 0.0f);
        h0[7] = fmaxf(fmaf(wxb.w, xi0, fmaf(wzb.w, zk0, bc.w)), 0.0f);
        h1[0] = fmaxf(fmaf(wxa.x, xi1, fmaf(wza.x, zk1, ba.x)), 0.0f);
        h1[1] = fmaxf(fmaf(wxa.y, xi1, fmaf(wza.y, zk1, ba.y)), 0.0f);
        h1[2] = fmaxf(fmaf(wxa.z, xi1, fmaf(wza.z, zk1, ba.z)), 0.0f);
        h1[3] = fmaxf(fmaf(wxa.w, xi1, fmaf(wza.w, zk1, ba.w)), 0.0f);
        h1[4] = fmaxf(fmaf(wxb.x, xi1, fmaf(wzb.x, zk1, bc.x)), 0.0f);
        h1[5] = fmaxf(fmaf(wxb.y, xi1, fmaf(wzb.y, zk1, bc.y)), 0.0f);
        h1[6] = fmaxf(fmaf(wxb.z, xi1, fmaf(wzb.z, zk1, bc.z)), 0.0f);
        h1[7] = fmaxf(fmaf(wxb.w, xi1, fmaf(wzb.w, zk1, bc.w)), 0.0f);

        ull t0[8], t1[8];
        {
            const ulonglong2* pb = pb1v + pl * 4;
            ulonglong2 q;
            q = pb[0]; t0[0] = q.x; t0[1] = q.y; t1[0] = q.x; t1[1] = q.y;
            q = pb[1]; t0[2] = q.x; t0[3] = q.y; t1[2] = q.x; t1[3] = q.y;
            q = pb[2]; t0[4] = q.x; t0[5] = q.y; t1[4] = q.x; t1[5] = q.y;
            q = pb[3]; t0[6] = q.x; t0[7] = q.y; t1[6] = q.x; t1[7] = q.y;
        }

        #pragma unroll
        for (int j = 0; j < 8; ++j) {
            const ulonglong2* wv = pw1v + (pl * 8 + j) * 4;
            ulonglong2 wA = wv[0], wB = wv[1], wC = wv[2], wD = wv[3];
            ull hv0 = pack2(h0[j], h0[j]);
            ull hv1 = pack2(h1[j], h1[j]);
            t0[0] = fma2(hv0, wA.x, t0[0]); t0[1] = fma2(hv0, wA.y, t0[1]);
            t0[2] = fma2(hv0, wB.x, t0[2]); t0[3] = fma2(hv0, wB.y, t0[3]);
            t0[4] = fma2(hv0, wC.x, t0[4]); t0[5] = fma2(hv0, wC.y, t0[5]);
            t0[6] = fma2(hv0, wD.x, t0[6]); t0[7] = fma2(hv0, wD.y, t0[7]);
            t1[0] = fma2(hv1, wA.x, t1[0]); t1[1] = fma2(hv1, wA.y, t1[1]);
            t1[2] = fma2(hv1, wB.x, t1[2]); t1[3] = fma2(hv1, wB.y, t1[3]);
            t1[4] = fma2(hv1, wC.x, t1[4]); t1[5] = fma2(hv1, wC.y, t1[5]);
            t1[6] = fma2(hv1, wD.x, t1[6]); t1[7] = fma2(hv1, wD.y, t1[7]);
        }

        float4 q0 = pw24[pl * 4 + 0];
        float4 q1 = pw24[pl * 4 + 1];
        float4 q2 = pw24[pl * 4 + 2];
        float4 q3 = pw24[pl * 4 + 3];
        float lo, hi;
        unpack2(t0[0], lo, hi);
        outA0 = fmaf(fmaxf(lo, 0.f), q0.x, outA0); outB0 = fmaf(fmaxf(hi, 0.f), q0.y, outB0);
        unpack2(t0[1], lo, hi);
        outA0 = fmaf(fmaxf(lo, 0.f), q0.z, outA0); outB0 = fmaf(fmaxf(hi, 0.f), q0.w, outB0);
        unpack2(t0[2], lo, hi);
        outA0 = fmaf(fmaxf(lo, 0.f), q1.x, outA0); outB0 = fmaf(fmaxf(hi, 0.f), q1.y, outB0);
        unpack2(t0[3], lo, hi);
        outA0 = fmaf(fmaxf(lo, 0.f), q1.z, outA0); outB0 = fmaf(fmaxf(hi, 0.f), q1.w, outB0);
        unpack2(t0[4], lo, hi);
        outA0 = fmaf(fmaxf(lo, 0.f), q2.x, outA0); outB0 = fmaf(fmaxf(hi, 0.f), q2.y, outB0);
        unpack2(t0[5], lo, hi);
        outA0 = fmaf(fmaxf(lo, 0.f), q2.z, outA0); outB0 = fmaf(fmaxf(hi, 0.f), q2.w, outB0);
        unpack2(t0[6], lo, hi);
        outA0 = fmaf(fmaxf(lo, 0.f), q3.x, outA0); outB0 = fmaf(fmaxf(hi, 0.f), q3.y, outB0);
        unpack2(t0[7], lo, hi);
        outA0 = fmaf(fmaxf(lo, 0.f), q3.z, outA0); outB0 = fmaf(fmaxf(hi, 0.f), q3.w, outB0);

        unpack2(t1[0], lo, hi);
        outA1 = fmaf(fmaxf(lo, 0.f), q0.x, outA1); outB1 = fmaf(fmaxf(hi, 0.f), q0.y, outB1);
        unpack2(t1[1], lo, hi);
        outA1 = fmaf(fmaxf(lo, 0.f), q0.z, outA1); outB1 = fmaf(fmaxf(hi, 0.f), q0.w, outB1);
        unpack2(t1[2], lo, hi);
        outA1 = fmaf(fmaxf(lo, 0.f), q1.x, outA1); outB1 = fmaf(fmaxf(hi, 0.f), q1.y, outB1);
        unpack2(t1[3], lo, hi);
        outA1 = fmaf(fmaxf(lo, 0.f), q1.z, outA1); outB1 = fmaf(fmaxf(hi, 0.f), q1.w, outB1);
        unpack2(t1[4], lo, hi);
        outA1 = fmaf(fmaxf(lo, 0.f), q2.x, outA1); outB1 = fmaf(fmaxf(hi, 0.f), q2.y, outB1);
        unpack2(t1[5], lo, hi);
        outA1 = fmaf(fmaxf(lo, 0.f), q2.z, outA1); outB1 = fmaf(fmaxf(hi, 0.f), q2.w, outB1);
        unpack2(t1[6], lo, hi);
        outA1 = fmaf(fmaxf(lo, 0.f), q3.x, outA1); outB1 = fmaf(fmaxf(hi, 0.f), q3.y, outB1);
        unpack2(t1[7], lo, hi);
        outA1 = fmaf(fmaxf(lo, 0.f), q3.z, outA1); outB1 = fmaf(fmaxf(hi, 0.f), q3.w, outB1);

        zk = zkn;
    }

    float2 o2;
    o2.x = outA0 + outB0;
    o2.y = outA1 + outB1;
    ((float2*)(g_partial + (size_t)chunk * BATCH + g0))[tid] = o2;
}

// ---------------------------------------------------------------------------
// Kernel 3: deterministic final reduction over 34 partial slices.
// ---------------------------------------------------------------------------
__global__ __launch_bounds__(256)
void reduce_kernel(float* __restrict__ out)
{
    const int b = blockIdx.x * 256 + threadIdx.x;
    float s = 0.0f;
    #pragma unroll
    for (int c = 0; c < PK_NCHUNK + 2; ++c)
        s += g_partial[c * BATCH + b];
    out[b] = s;
}

// ---------------------------------------------------------------------------
extern "C" void kernel_launch(void* const* d_in, const int* in_sizes, int n_in,
                              void* d_out, int out_size)
{
    const float* x   = (const float*)d_in[0];
    const float* z   = (const float*)d_in[1];
    const float* xw1 = (const float*)d_in[2];
    const float* xb1 = (const float*)d_in[3];
    const float* xw2 = (const float*)d_in[4];
    const float* xb2 = (const float*)d_in[5];
    const float* xw3 = (const float*)d_in[6];
    const float* xb3 = (const float*)d_in[7];
    const float* zw1 = (const float*)d_in[8];
    const float* zb1 = (const float*)d_in[9];
    const float* zw2 = (const float*)d_in[10];
    const float* zb2 = (const float*)d_in[11];
    const float* zw3 = (const float*)d_in[12];
    const float* zb3 = (const float*)d_in[13];
    const float* xzw = (const float*)d_in[14];
    const float* xzb = (const float*)d_in[15];
    const float* pw1 = (const float*)d_in[16];
    const float* pb1 = (const float*)d_in[17];
    const float* pw2 = (const float*)d_in[18];
    float* out = (float*)d_out;

    const size_t smem_mlp = 22848u * sizeof(float);   // 91392 B

    cudaFuncSetAttribute(mlp_kernel, cudaFuncAttributeMaxDynamicSharedMemorySize, (int)smem_mlp);

    transpose_kernel<<<BATCH / 64, 256>>>(x, z);
    pair_kernel<<<dim3(PK_NTILE, PK_NCHUNK), 128>>>(xzw, xzb, pw1, pb1, pw2);
    mlp_kernel<<<dim3(MK_NTILE, 2), 128, smem_mlp>>>(x, z,
        xw1, xb1, xw2, xb2, xw3, xb3,
        zw1, zb1, zw2, zb2, zw3, zb3);
    reduce_kernel<<<BATCH / 256, 256>>>(out);
}

// round 4
// speedup vs baseline: 1.9506x; 1.0027x over previous
#include <cuda_runtime.h>
#include <cuda_bf16.h>

// Problem constants
#define BATCH   8192
#define R_DIM   8
#define PH_DIM  16
#define PAIRS   1024
#define OUT_U   8192   // PAIRS * R

// Pair kernel tiling
#define PK_TILE      256   // samples per CTA (2 adjacent per thread, packed)
#define PK_CHUNK     32    // pairs per CTA (one x-column per chunk)
#define PK_NCHUNK    (PAIRS / PK_CHUNK)      // 32
#define PK_NTILE     (BATCH / PK_TILE)       // 32

// MLP kernel tiling
#define MK_TILE      64
#define MK_NTILE     (BATCH / MK_TILE)       // 128

// Deterministic partial buffer: 32 interaction chunks + X + Z
__device__ float g_partial[(PK_NCHUNK + 2) * BATCH];
// Transposed inputs: [32][8192]
__device__ float g_xT[32 * BATCH];
__device__ float g_zT[32 * BATCH];

typedef unsigned long long ull;

// ---- packed f32x2 helpers ---------------------------------------------------
__device__ __forceinline__ ull pack2(float lo, float hi) {
    ull r;
    asm("mov.b64 %0, {%1, %2};" : "=l"(r) : "f"(lo), "f"(hi));
    return r;
}
__device__ __forceinline__ void unpack2(ull v, float& lo, float& hi) {
    asm("mov.b64 {%0, %1}, %2;" : "=f"(lo), "=f"(hi) : "l"(v));
}
__device__ __forceinline__ ull fma2(ull a, ull b, ull c) {
    ull d;
    asm("fma.rn.f32x2 %0, %1, %2, %3;" : "=l"(d) : "l"(a), "l"(b), "l"(c));
    return d;
}
__device__ __forceinline__ ull relu2(ull v) {
    float a, b;
    unpack2(v, a, b);
    return pack2(fmaxf(a, 0.0f), fmaxf(b, 0.0f));
}
__device__ __forceinline__ ull dup_lo(ull v) {
    float a, b; unpack2(v, a, b); return pack2(a, a);
}
__device__ __forceinline__ ull dup_hi(ull v) {
    float a, b; unpack2(v, a, b); return pack2(b, b);
}

// ---------------------------------------------------------------------------
// Kernel 0: transpose x,z [8192][32] -> [32][8192]
// ---------------------------------------------------------------------------
__global__ __launch_bounds__(256)
void transpose_kernel(const float* __restrict__ x, const float* __restrict__ z)
{
    __shared__ float tx[64 * 33];
    __shared__ float tz[64 * 33];
    const int tid = threadIdx.x;
    const int g0  = blockIdx.x * 64;

    for (int idx = tid; idx < 64 * 32; idx += 256) {
        int s = idx >> 5, c = idx & 31;
        tx[s * 33 + c] = x[(size_t)g0 * 32 + idx];
        tz[s * 33 + c] = z[(size_t)g0 * 32 + idx];
    }
    __syncthreads();
    for (int idx = tid; idx < 64 * 32; idx += 256) {
        int c = idx >> 6, s = idx & 63;
        g_xT[(size_t)c * BATCH + g0 + s] = tx[s * 33 + c];
        g_zT[(size_t)c * BATCH + g0 + s] = tz[s * 33 + c];
    }
}

// ---------------------------------------------------------------------------
// Kernel 1: main-effect MLPs (32->128->64->1). blockIdx.y = part (x or z).
// ---------------------------------------------------------------------------
__global__ __launch_bounds__(128)
void mlp_kernel(const float* __restrict__ x, const float* __restrict__ z,
                const float* __restrict__ xw1, const float* __restrict__ xb1,
                const float* __restrict__ xw2, const float* __restrict__ xb2,
                const float* __restrict__ xw3, const float* __restrict__ xb3,
                const float* __restrict__ zw1, const float* __restrict__ zb1,
                const float* __restrict__ zw2, const float* __restrict__ zb2,
                const float* __restrict__ zw3, const float* __restrict__ zb3)
{
    extern __shared__ float sm[];
    float* in_sm = sm;                 // 64*32   = 2048
    float* h1_sm = sm + 2048;          // 64*128  = 8192
    float* w2_sm = sm + 10240;         // 128*64  = 8192
    float* h2_sm = sm + 18432;         // 64*68   = 4352
    float* w3_sm = sm + 22784;         // 64

    const int tid  = threadIdx.x;
    const int tile = blockIdx.x;
    const int part = blockIdx.y;
    const int g0   = tile * MK_TILE;

    const float* in = part ? z   : x;
    const float* w1 = part ? zw1 : xw1;
    const float* b1 = part ? zb1 : xb1;
    const float* w2 = part ? zw2 : xw2;
    const float* b2 = part ? zb2 : xb2;
    const float* w3 = part ? zw3 : xw3;
    const float* b3 = part ? zb3 : xb3;

    for (int idx = tid; idx < MK_TILE * 32; idx += 128)
        in_sm[idx] = in[(size_t)g0 * 32 + idx];
    for (int idx = tid; idx < 128 * 64; idx += 128)
        w2_sm[idx] = w2[idx];
    if (tid < 64) w3_sm[tid] = w3[tid];

    float wc[32];
    #pragma unroll
    for (int l = 0; l < 32; ++l) wc[l] = w1[l * 128 + tid];
    const float bc = b1[tid];

    __syncthreads();

    // ---- phase 1 ----
    for (int s = 0; s < MK_TILE; ++s) {
        float acc = bc;
        const float4* xr = (const float4*)(in_sm + s * 32);
        #pragma unroll
        for (int l4 = 0; l4 < 8; ++l4) {
            float4 v = xr[l4];
            acc = fmaf(v.x, wc[l4 * 4 + 0], acc);
            acc = fmaf(v.y, wc[l4 * 4 + 1], acc);
            acc = fmaf(v.z, wc[l4 * 4 + 2], acc);
            acc = fmaf(v.w, wc[l4 * 4 + 3], acc);
        }
        h1_sm[s * 128 + tid] = fmaxf(acc, 0.0f);
    }
    __syncthreads();

    // ---- phase 2: loop-swapped, f32x2 ----
    {
        const int oq = tid & 15;
        const int sg = tid >> 4;
        float4 bb = ((const float4*)b2)[oq];
        ull accA[8], accB[8];
        const ull bA = pack2(bb.x, bb.y);
        const ull bB = pack2(bb.z, bb.w);
        #pragma unroll
        for (int ss = 0; ss < 8; ++ss) { accA[ss] = bA; accB[ss] = bB; }

        const float4* w24   = (const float4*)w2_sm;
        const float4* hbase = (const float4*)(h1_sm + sg * 8 * 128);

        #pragma unroll 2
        for (int l4 = 0; l4 < 32; ++l4) {
            float4 wA = w24[(l4 * 4 + 0) * 16 + oq];
            float4 wB = w24[(l4 * 4 + 1) * 16 + oq];
            float4 wC = w24[(l4 * 4 + 2) * 16 + oq];
            float4 wD = w24[(l4 * 4 + 3) * 16 + oq];
            const ulonglong2 wAp = *(const ulonglong2*)&wA;
            const ulonglong2 wBp = *(const ulonglong2*)&wB;
            const ulonglong2 wCp = *(const ulonglong2*)&wC;
            const ulonglong2 wDp = *(const ulonglong2*)&wD;
            #pragma unroll
            for (int ss = 0; ss < 8; ++ss) {
                float4 hv = hbase[ss * 32 + l4];
                ull hx = pack2(hv.x, hv.x);
                ull hy = pack2(hv.y, hv.y);
                ull hz = pack2(hv.z, hv.z);
                ull hw = pack2(hv.w, hv.w);
                accA[ss] = fma2(hx, wAp.x, accA[ss]); accB[ss] = fma2(hx, wAp.y, accB[ss]);
                accA[ss] = fma2(hy, wBp.x, accA[ss]); accB[ss] = fma2(hy, wBp.y, accB[ss]);
                accA[ss] = fma2(hz, wCp.x, accA[ss]); accB[ss] = fma2(hz, wCp.y, accB[ss]);
                accA[ss] = fma2(hw, wDp.x, accA[ss]); accB[ss] = fma2(hw, wDp.y, accB[ss]);
            }
        }
        #pragma unroll
        for (int ss = 0; ss < 8; ++ss) {
            const int s = sg * 8 + ss;
            float a0, a1, a2, a3;
            unpack2(accA[ss], a0, a1);
            unpack2(accB[ss], a2, a3);
            float4 r;
            r.x = fmaxf(a0, 0.0f); r.y = fmaxf(a1, 0.0f);
            r.z = fmaxf(a2, 0.0f); r.w = fmaxf(a3, 0.0f);
            *(float4*)(h2_sm + s * 68 + oq * 4) = r;
        }
    }
    __syncthreads();

    // ---- phase 3 ----
    if (tid < MK_TILE) {
        const int s = tid;
        float acc = b3[0];
        const float* hr = h2_sm + s * 68;
        #pragma unroll
        for (int o = 0; o < 64; ++o) acc = fmaf(hr[o], w3_sm[o], acc);
        g_partial[(PK_NCHUNK + part) * BATCH + g0 + s] = acc;
    }
}

// ---------------------------------------------------------------------------
// Kernel 2: structured interaction + per-pair MLPs, fully f32x2-packed.
// grid = (32 sample tiles, 32 pair chunks). 128 threads, samples (2t, 2t+1)
// packed into one 64-bit lane. h-stage & out-stage packed; pw1 ph-packed.
// ---------------------------------------------------------------------------
__global__ __launch_bounds__(128, 4)
void pair_kernel(const float* __restrict__ xzw, const float* __restrict__ xzb,
                 const float* __restrict__ pw1, const float* __restrict__ pb1,
                 const float* __restrict__ pw2)
{
    __shared__ __align__(16) float sm[6656];   // 26624 B
    float* wxd_sm = sm;            // 512 (32 pairs x 8 x dup2)
    float* wzd_sm = sm + 512;      // 512
    float* bbd_sm = sm + 1024;     // 512
    float* pw1_sm = sm + 1536;     // 4096
    float* pb1_sm = sm + 5632;     // 512
    float* pw2_sm = sm + 6144;     // 512

    const int tid   = threadIdx.x;
    const int tile  = blockIdx.x;
    const int chunk = blockIdx.y;
    const int g0    = tile * PK_TILE;
    const int p0    = chunk * PK_CHUNK;

    // stage duplicated h-stage weights
    for (int idx = tid; idx < PK_CHUNK * R_DIM; idx += 128) {
        int col = p0 * R_DIM + idx;
        int k   = idx >> 3;                 // pair index within chunk == z index
        float wx = xzw[(size_t)chunk * OUT_U + col];
        float wz = xzw[(size_t)(32 + k) * OUT_U + col];
        float bb = xzb[col];
        wxd_sm[2 * idx] = wx; wxd_sm[2 * idx + 1] = wx;
        wzd_sm[2 * idx] = wz; wzd_sm[2 * idx + 1] = wz;
        bbd_sm[2 * idx] = bb; bbd_sm[2 * idx + 1] = bb;
    }
    for (int idx = tid; idx < PK_CHUNK * R_DIM * PH_DIM; idx += 128)
        pw1_sm[idx] = pw1[(size_t)p0 * R_DIM * PH_DIM + idx];
    for (int idx = tid; idx < PK_CHUNK * PH_DIM; idx += 128) {
        pb1_sm[idx] = pb1[(size_t)p0 * PH_DIM + idx];
        pw2_sm[idx] = pw2[(size_t)p0 * PH_DIM + idx];
    }

    // packed sample pair (s0 = g0 + 2*tid, s1 = s0 + 1)
    const float2 xi2 = ((const float2*)(g_xT + (size_t)chunk * BATCH + g0))[tid];
    const ull xi = pack2(xi2.x, xi2.y);
    const float2* zT2 = (const float2*)(g_zT + g0) + tid;  // column stride = 4096 float2

    __syncthreads();

    const ulonglong2* wxd2 = (const ulonglong2*)wxd_sm;   // 4 per pair
    const ulonglong2* wzd2 = (const ulonglong2*)wzd_sm;
    const ulonglong2* bbd2 = (const ulonglong2*)bbd_sm;
    const ulonglong2* pw1v = (const ulonglong2*)pw1_sm;   // 4 per (pair,j)
    const ulonglong2* pb1v = (const ulonglong2*)pb1_sm;   // 4 per pair
    const ulonglong2* pw2v = (const ulonglong2*)pw2_sm;   // 4 per pair

    // packed out accumulators (ph-packed): 4 chains per sample
    ull o0[4], o1[4];
    #pragma unroll
    for (int k = 0; k < 4; ++k) { o0[k] = 0ull; o1[k] = 0ull; }

    float2 zkf = zT2[0];

    #pragma unroll 1
    for (int pl = 0; pl < PK_CHUNK; ++pl) {
        float2 zkn = zT2[((pl + 1) & 31) * (BATCH / 2)];   // prefetch next column
        const ull zk = pack2(zkf.x, zkf.y);

        // h_pair[j] = relu2(wx*xi + wz*zk + b), packed over samples
        ulonglong2 wxA = wxd2[pl * 4 + 0], wxB = wxd2[pl * 4 + 1];
        ulonglong2 wxC = wxd2[pl * 4 + 2], wxD = wxd2[pl * 4 + 3];
        ulonglong2 wzA = wzd2[pl * 4 + 0], wzB = wzd2[pl * 4 + 1];
        ulonglong2 wzC = wzd2[pl * 4 + 2], wzD = wzd2[pl * 4 + 3];
        ulonglong2 bbA = bbd2[pl * 4 + 0], bbB = bbd2[pl * 4 + 1];
        ulonglong2 bbC = bbd2[pl * 4 + 2], bbD = bbd2[pl * 4 + 3];
        ull h[8];
        h[0] = relu2(fma2(wxA.x, xi, fma2(wzA.x, zk, bbA.x)));
        h[1] = relu2(fma2(wxA.y, xi, fma2(wzA.y, zk, bbA.y)));
        h[2] = relu2(fma2(wxB.x, xi, fma2(wzB.x, zk, bbB.x)));
        h[3] = relu2(fma2(wxB.y, xi, fma2(wzB.y, zk, bbB.y)));
        h[4] = relu2(fma2(wxC.x, xi, fma2(wzC.x, zk, bbC.x)));
        h[5] = relu2(fma2(wxC.y, xi, fma2(wzC.y, zk, bbC.y)));
        h[6] = relu2(fma2(wxD.x, xi, fma2(wzD.x, zk, bbD.x)));
        h[7] = relu2(fma2(wxD.y, xi, fma2(wzD.y, zk, bbD.y)));

        // t (ph-packed, 8 ull per sample), init from pb1
        ull t0[8], t1[8];
        {
            ulonglong2 q;
            q = pb1v[pl * 4 + 0]; t0[0] = q.x; t0[1] = q.y; t1[0] = q.x; t1[1] = q.y;
            q = pb1v[pl * 4 + 1]; t0[2] = q.x; t0[3] = q.y; t1[2] = q.x; t1[3] = q.y;
            q = pb1v[pl * 4 + 2]; t0[4] = q.x; t0[5] = q.y; t1[4] = q.x; t1[5] = q.y;
            q = pb1v[pl * 4 + 3]; t0[6] = q.x; t0[7] = q.y; t1[6] = q.x; t1[7] = q.y;
        }

        #pragma unroll
        for (int j = 0; j < 8; ++j) {
            const ulonglong2* wv = pw1v + (pl * 8 + j) * 4;
            ulonglong2 wA = wv[0], wB = wv[1], wC = wv[2], wD = wv[3];
            ull hv0 = dup_lo(h[j]);
            ull hv1 = dup_hi(h[j]);
            t0[0] = fma2(hv0, wA.x, t0[0]); t0[1] = fma2(hv0, wA.y, t0[1]);
            t0[2] = fma2(hv0, wB.x, t0[2]); t0[3] = fma2(hv0, wB.y, t0[3]);
            t0[4] = fma2(hv0, wC.x, t0[4]); t0[5] = fma2(hv0, wC.y, t0[5]);
            t0[6] = fma2(hv0, wD.x, t0[6]); t0[7] = fma2(hv0, wD.y, t0[7]);
            t1[0] = fma2(hv1, wA.x, t1[0]); t1[1] = fma2(hv1, wA.y, t1[1]);
            t1[2] = fma2(hv1, wB.x, t1[2]); t1[3] = fma2(hv1, wB.y, t1[3]);
            t1[4] = fma2(hv1, wC.x, t1[4]); t1[5] = fma2(hv1, wC.y, t1[5]);
            t1[6] = fma2(hv1, wD.x, t1[6]); t1[7] = fma2(hv1, wD.y, t1[7]);
        }

        // out += relu2(t) * pw2  (stay packed; 4 chains per sample)
        ulonglong2 qA = pw2v[pl * 4 + 0], qB = pw2v[pl * 4 + 1];
        ulonglong2 qC = pw2v[pl * 4 + 2], qD = pw2v[pl * 4 + 3];
        o0[0] = fma2(relu2(t0[0]), qA.x, o0[0]);
        o0[1] = fma2(relu2(t0[1]), qA.y, o0[1]);
        o0[2] = fma2(relu2(t0[2]), qB.x, o0[2]);
        o0[3] = fma2(relu2(t0[3]), qB.y, o0[3]);
        o0[0] = fma2(relu2(t0[4]), qC.x, o0[0]);
        o0[1] = fma2(relu2(t0[5]), qC.y, o0[1]);
        o0[2] = fma2(relu2(t0[6]), qD.x, o0[2]);
        o0[3] = fma2(relu2(t0[7]), qD.y, o0[3]);
        o1[0] = fma2(relu2(t1[0]), qA.x, o1[0]);
        o1[1] = fma2(relu2(t1[1]), qA.y, o1[1]);
        o1[2] = fma2(relu2(t1[2]), qB.x, o1[2]);
        o1[3] = fma2(relu2(t1[3]), qB.y, o1[3]);
        o1[0] = fma2(relu2(t1[4]), qC.x, o1[0]);
        o1[1] = fma2(relu2(t1[5]), qC.y, o1[1]);
        o1[2] = fma2(relu2(t1[6]), qD.x, o1[2]);
        o1[3] = fma2(relu2(t1[7]), qD.y, o1[3]);

        zkf = zkn;
    }

    // horizontal sums (fixed order -> deterministic)
    float a, b, s0, s1;
    unpack2(o0[0], a, b); s0 = a + b;
    unpack2(o0[1], a, b); s0 += a + b;
    unpack2(o0[2], a, b); s0 += a + b;
    unpack2(o0[3], a, b); s0 += a + b;
    unpack2(o1[0], a, b); s1 = a + b;
    unpack2(o1[1], a, b); s1 += a + b;
    unpack2(o1[2], a, b); s1 += a + b;
    unpack2(o1[3], a, b); s1 += a + b;

    float2 o2; o2.x = s0; o2.y = s1;
    ((float2*)(g_partial + (size_t)chunk * BATCH + g0))[tid] = o2;
}

// ---------------------------------------------------------------------------
// Kernel 3: deterministic final reduction over 34 partial slices.
// ---------------------------------------------------------------------------
__global__ __launch_bounds__(256)
void reduce_kernel(float* __restrict__ out)
{
    const int b = blockIdx.x * 256 + threadIdx.x;
    float s = 0.0f;
    #pragma unroll
    for (int c = 0; c < PK_NCHUNK + 2; ++c)
        s += g_partial[c * BATCH + b];
    out[b] = s;
}

// ---------------------------------------------------------------------------
extern "C" void kernel_launch(void* const* d_in, const int* in_sizes, int n_in,
                              void* d_out, int out_size)
{
    const float* x   = (const float*)d_in[0];
    const float* z   = (const float*)d_in[1];
    const float* xw1 = (const float*)d_in[2];
    const float* xb1 = (const float*)d_in[3];
    const float* xw2 = (const float*)d_in[4];
    const float* xb2 = (const float*)d_in[5];
    const float* xw3 = (const float*)d_in[6];
    const float* xb3 = (const float*)d_in[7];
    const float* zw1 = (const float*)d_in[8];
    const float* zb1 = (const float*)d_in[9];
    const float* zw2 = (const float*)d_in[10];
    const float* zb2 = (const float*)d_in[11];
    const float* zw3 = (const float*)d_in[12];
    const float* zb3 = (const float*)d_in[13];
    const float* xzw = (const float*)d_in[14];
    const float* xzb = (const float*)d_in[15];
    const float* pw1 = (const float*)d_in[16];
    const float* pb1 = (const float*)d_in[17];
    const float* pw2 = (const float*)d_in[18];
    float* out = (float*)d_out;

    // side stream + events for fork/join (host resources, created once;
    // no device memory involved)
    static cudaStream_t s2 = nullptr;
    static cudaEvent_t  e_fork = nullptr, e_join = nullptr;
    if (s2 == nullptr) {
        cudaStreamCreateWithFlags(&s2, cudaStreamNonBlocking);
        cudaEventCreateWithFlags(&e_fork, cudaEventDisableTiming);
        cudaEventCreateWithFlags(&e_join, cudaEventDisableTiming);
    }

    const size_t smem_mlp = 22848u * sizeof(float);   // 91392 B
    cudaFuncSetAttribute(mlp_kernel, cudaFuncAttributeMaxDynamicSharedMemorySize, (int)smem_mlp);

    // fork: mlp on side stream, overlapped with transpose+pair on main stream
    cudaEventRecord(e_fork, 0);
    cudaStreamWaitEvent(s2, e_fork, 0);
    mlp_kernel<<<dim3(MK_NTILE, 2), 128, smem_mlp, s2>>>(x, z,
        xw1, xb1, xw2, xb2, xw3, xb3,
        zw1, zb1, zw2, zb2, zw3, zb3);
    cudaEventRecord(e_join, s2);

    transpose_kernel<<<BATCH / 64, 256>>>(x, z);
    pair_kernel<<<dim3(PK_NTILE, PK_NCHUNK), 128>>>(xzw, xzb, pw1, pb1, pw2);

    // join, then reduce
    cudaStreamWaitEvent(0, e_join, 0);
    reduce_kernel<<<BATCH / 256, 256>>>(out);
}